// round 11
// baseline (speedup 1.0000x reference)
#include <cuda_runtime.h>

// Problem constants (fixed by the reference)
#define BB 1024
#define NN 16
#define TT 256
#define TPB 128                     // 128 threads = 128 (b,t) pairs (best size)
#define GRID (BB * (TT / TPB))      // 2048 blocks, 2 per batch b

#define TRI(i, j) ((i) * ((i) + 1) / 2 + (j))   // packed 4x4 lower-tri index
#define LDS_(p) __ldcs(p)           // streaming load: evict-first, no L1 alloc

// Scratch for deterministic single-launch reduction (no cudaMalloc allowed)
__device__ float g_partials[GRID];
__device__ unsigned int g_count = 0;   // self-resetting arrival counter

// Factor a width-4 panel: T = 4x4 packed lower tri (diagonal block),
// R = NR x 4 rows below it. Fused forward solve on y[BASE..]. Pivots >= 1.
#define FACTOR_PANEL(T, R, NR, BASE)                                        \
    _Pragma("unroll")                                                       \
    for (int j = 0; j < 4; ++j) {                                           \
        const float s = T[TRI(j, j)];                                       \
        pivprod *= s;                                                       \
        const float invd = rsqrtf(s);                                       \
        y[BASE + j] *= invd;                                                \
        quad = fmaf(y[BASE + j], y[BASE + j], quad);                        \
        _Pragma("unroll")                                                   \
        for (int i = j + 1; i < 4; ++i) T[TRI(i, j)] *= invd;               \
        _Pragma("unroll")                                                   \
        for (int r = 0; r < NR; ++r) R[r][j] *= invd;                       \
        _Pragma("unroll")                                                   \
        for (int i = j + 1; i < 4; ++i)                                     \
            y[BASE + i] = fmaf(-T[TRI(i, j)], y[BASE + j], y[BASE + i]);    \
        _Pragma("unroll")                                                   \
        for (int r = 0; r < NR; ++r)                                        \
            y[BASE + 4 + r] = fmaf(-R[r][j], y[BASE + j], y[BASE + 4 + r]); \
        _Pragma("unroll")                                                   \
        for (int k = j + 1; k < 4; ++k) {                                   \
            const float ckj = T[TRI(k, j)];                                 \
            _Pragma("unroll")                                               \
            for (int i = k; i < 4; ++i)                                     \
                T[TRI(i, k)] = fmaf(-T[TRI(i, j)], ckj, T[TRI(i, k)]);      \
            _Pragma("unroll")                                               \
            for (int r = 0; r < NR; ++r)                                    \
                R[r][k] = fmaf(-R[r][j], ckj, R[r][k]);                     \
        }                                                                   \
    }

__global__ __launch_bounds__(TPB, 4) void gll_p4_kernel(
    const float* __restrict__ pred,
    const float* __restrict__ targ,
    const float* __restrict__ cov,
    float* __restrict__ out)
{
    const int tid = threadIdx.x;
    const int bid = blockIdx.x;
    const int b   = bid >> 1;
    const int t   = ((bid & 1) << 7) + tid;   // this thread's time index

    // cov plane (i,j) element t at cov[((b*16+i)*16+j)*256 + t]; consecutive
    // tid -> consecutive t -> fully coalesced 128B warp runs per plane.
    const float* covb = cov + ((size_t)b * NN * NN) * TT + t;

    float pivprod = 1.0f;
    float quad    = 0.0f;

    // ---- diff vector (streaming loads: single-touch data, skip L1 alloc)
    float y[NN];
#pragma unroll
    for (int i = 0; i < NN; ++i) {
        const int off = (b * NN + i) * TT + t;
        y[i] = LDS_(pred + off) - LDS_(targ + off);
    }

    // ================= Panel 1: cols 0-3 =================
    float T1[10];                 // rows 0-3, packed lower tri
    float R1[12][4];              // rows 4-15 x cols 0-3
#pragma unroll
    for (int i = 0; i < 4; ++i)
#pragma unroll
        for (int j = 0; j <= i; ++j)
            T1[TRI(i, j)] = LDS_(covb + (i * NN + j) * TT);
#pragma unroll
    for (int r = 0; r < 12; ++r)
#pragma unroll
        for (int c = 0; c < 4; ++c)
            R1[r][c] = LDS_(covb + ((4 + r) * NN + c) * TT);

    FACTOR_PANEL(T1, R1, 12, 0)   // T1 dead after this

    // ================= Panel 2: cols 4-7 =================
    float T2[10];                 // rows 4-7 (local q), packed lower tri
    float R2[8][4];               // rows 8-15 (local r) x cols 4-7
#pragma unroll
    for (int q = 0; q < 4; ++q)
#pragma unroll
        for (int c = 0; c <= q; ++c)
            T2[TRI(q, c)] = LDS_(covb + ((4 + q) * NN + (4 + c)) * TT);
#pragma unroll
    for (int r = 0; r < 8; ++r)
#pragma unroll
        for (int c = 0; c < 4; ++c)
            R2[r][c] = LDS_(covb + ((8 + r) * NN + (4 + c)) * TT);

    // syrk update from panel 1 (L rows 4-15 live in R1)
#pragma unroll
    for (int c = 0; c < 4; ++c) {
#pragma unroll
        for (int m = 0; m < 4; ++m) {
            const float lcm = R1[c][m];                    // L[4+c][m]
#pragma unroll
            for (int q = c; q < 4; ++q)
                T2[TRI(q, c)] = fmaf(-R1[q][m], lcm, T2[TRI(q, c)]);
#pragma unroll
            for (int r = 0; r < 8; ++r)
                R2[r][c] = fmaf(-R1[r + 4][m], lcm, R2[r][c]);
        }
    }
    FACTOR_PANEL(T2, R2, 8, 4)

    // ================= Panel 3: cols 8-11 =================
    float T3[10];                 // rows 8-11, packed lower tri
    float R3[4][4];               // rows 12-15 x cols 8-11
#pragma unroll
    for (int q = 0; q < 4; ++q)
#pragma unroll
        for (int c = 0; c <= q; ++c)
            T3[TRI(q, c)] = LDS_(covb + ((8 + q) * NN + (8 + c)) * TT);
#pragma unroll
    for (int r = 0; r < 4; ++r)
#pragma unroll
        for (int c = 0; c < 4; ++c)
            R3[r][c] = LDS_(covb + ((12 + r) * NN + (8 + c)) * TT);

    // updates from panel 1 (R1 rows 4..11 ~ global 8-15) and panel 2 (R2)
#pragma unroll
    for (int c = 0; c < 4; ++c) {
#pragma unroll
        for (int m = 0; m < 4; ++m) {
            const float l1 = R1[c + 4][m];                 // L[8+c][m]
#pragma unroll
            for (int q = c; q < 4; ++q)
                T3[TRI(q, c)] = fmaf(-R1[q + 4][m], l1, T3[TRI(q, c)]);
#pragma unroll
            for (int r = 0; r < 4; ++r)
                R3[r][c] = fmaf(-R1[r + 8][m], l1, R3[r][c]);

            const float l2 = R2[c][m];                     // L[8+c][4+m]
#pragma unroll
            for (int q = c; q < 4; ++q)
                T3[TRI(q, c)] = fmaf(-R2[q][m], l2, T3[TRI(q, c)]);
#pragma unroll
            for (int r = 0; r < 4; ++r)
                R3[r][c] = fmaf(-R2[r + 4][m], l2, R3[r][c]);
        }
    }
    FACTOR_PANEL(T3, R3, 4, 8)

    // ================= Panel 4: cols 12-15 =================
    float T4[10];                 // rows 12-15, packed lower tri
#pragma unroll
    for (int q = 0; q < 4; ++q)
#pragma unroll
        for (int c = 0; c <= q; ++c)
            T4[TRI(q, c)] = LDS_(covb + ((12 + q) * NN + (12 + c)) * TT);

    // updates from panels 1-3 (rows 12-15: R1[8..11], R2[4..7], R3[0..3])
#pragma unroll
    for (int c = 0; c < 4; ++c) {
#pragma unroll
        for (int m = 0; m < 4; ++m) {
            const float l1 = R1[c + 8][m];
#pragma unroll
            for (int q = c; q < 4; ++q)
                T4[TRI(q, c)] = fmaf(-R1[q + 8][m], l1, T4[TRI(q, c)]);
            const float l2 = R2[c + 4][m];
#pragma unroll
            for (int q = c; q < 4; ++q)
                T4[TRI(q, c)] = fmaf(-R2[q + 4][m], l2, T4[TRI(q, c)]);
            const float l3 = R3[c][m];
#pragma unroll
            for (int q = c; q < 4; ++q)
                T4[TRI(q, c)] = fmaf(-R3[q][m], l3, T4[TRI(q, c)]);
        }
    }
    FACTOR_PANEL(T4, R3 /*dummy, NR=0*/, 0, 12)

    // pivprod = det(Sigma) >= 1, well within fp32 range -> one __logf.
    float v = quad + __logf(pivprod);

    // ---- In-block reduction: warp shuffles + 4-warp smem combine
    const int lane = tid & 31;
    const int wid  = tid >> 5;
#pragma unroll
    for (int o = 16; o > 0; o >>= 1) v += __shfl_down_sync(0xffffffffu, v, o);

    __shared__ float warpsum[TPB / 32];
    __shared__ bool  isLast;
    if (lane == 0) warpsum[wid] = v;
    __syncthreads();

    if (tid == 0) {
        float s = warpsum[0] + warpsum[1] + warpsum[2] + warpsum[3];
        g_partials[bid] = s;
        __threadfence();
        unsigned int c = atomicAdd(&g_count, 1u);
        isLast = (c == (unsigned int)(GRID - 1));
    }
    __syncthreads();

    // Last arriving block performs the deterministic final sum (fixed order).
    if (isLast) {
        float s = 0.0f;
#pragma unroll 8
        for (int i = tid; i < GRID; i += TPB) s += g_partials[i];
#pragma unroll
        for (int o = 16; o > 0; o >>= 1) s += __shfl_down_sync(0xffffffffu, s, o);
        if (lane == 0) warpsum[wid] = s;
        __syncthreads();
        if (tid == 0) {
            out[0] = (warpsum[0] + warpsum[1] + warpsum[2] + warpsum[3])
                     * (1.0f / (float)(BB * TT));
            g_count = 0;   // reset for the next graph replay
        }
    }
}

extern "C" void kernel_launch(void* const* d_in, const int* in_sizes, int n_in,
                              void* d_out, int out_size)
{
    const float* pred = (const float*)d_in[0];   // prediction [B,N,T]
    const float* targ = (const float*)d_in[1];   // target     [B,N,T]
    const float* cov  = (const float*)d_in[2];   // cov        [B,N,N,T]
    float* out = (float*)d_out;

    gll_p4_kernel<<<GRID, TPB>>>(pred, targ, cov, out);
}

// round 13
// speedup vs baseline: 1.1812x; 1.1812x over previous
#include <cuda_runtime.h>

// Problem constants (fixed by the reference)
#define BB 1024
#define NN 16
#define TT 256
#define TPB 128                     // empirically best block size
#define GRID (BB * (TT / TPB))      // 2048 blocks, 2 per batch b

// Pair-triangle storage: pair s holds rows (2s, 2s+1); slot (s,k) = column k,
// k = 0..2s+1. Offset s*s+s+k, 72 slots total (= 144 floats as 72 x f32x2).
#define PIX(s, k) ((s) * (s) + (s) + (k))

typedef unsigned long long u64;     // one packed f32x2 value (lo = row 2s)

// Scratch for deterministic single-launch reduction (no cudaMalloc allowed)
__device__ float g_partials[GRID];
__device__ unsigned int g_count = 0;   // self-resetting arrival counter

// ---- packed fp32x2 primitives (sm_103a; PTX-only, ptxas won't auto-fuse)
__device__ __forceinline__ u64 pack2(float lo, float hi) {
    u64 r; asm("mov.b64 %0, {%1, %2};" : "=l"(r) : "f"(lo), "f"(hi)); return r;
}
__device__ __forceinline__ void unpack2(u64 v, float& lo, float& hi) {
    asm("mov.b64 {%0, %1}, %2;" : "=f"(lo), "=f"(hi) : "l"(v));
}
__device__ __forceinline__ u64 fma2(u64 a, u64 b, u64 c) {   // a*b + c per lane
    u64 d; asm("fma.rn.f32x2 %0, %1, %2, %3;" : "=l"(d) : "l"(a), "l"(b), "l"(c));
    return d;
}
__device__ __forceinline__ u64 mul2(u64 a, u64 b) {
    u64 d; asm("mul.rn.f32x2 %0, %1, %2;" : "=l"(d) : "l"(a), "l"(b)); return d;
}

__global__ __launch_bounds__(TPB, 3) void gll_f32x2_kernel(
    const float* __restrict__ pred,
    const float* __restrict__ targ,
    const float* __restrict__ cov,
    float* __restrict__ out)
{
    const int tid = threadIdx.x;
    const int bid = blockIdx.x;
    const int b   = bid >> 1;
    const int t   = ((bid & 1) << 7) + tid;   // this thread's time index

    // cov plane (i,j) element t at cov[((b*16+i)*16+j)*256 + t]; consecutive
    // tid -> consecutive t -> fully coalesced 128B warp runs per plane.
    const float* covb = cov + ((size_t)b * NN * NN) * TT + t;

    u64 P[72];   // paired lower triangle (rows 2s/2s+1 per slot)
    u64 Y[8];    // paired diff vector

    // ---- Front-batched loads (R2 memory shape: the proven-best pattern).
    // Dead lane (row 2s, col 2s+1) is zeroed; packed lanes are independent,
    // and the dead lanes provably never feed a live lane in the math below.
#pragma unroll
    for (int s = 0; s < 8; ++s) {
        const int r0 = 2 * s, r1 = 2 * s + 1;
        const int o0 = (b * NN + r0) * TT + t;
        const int o1 = (b * NN + r1) * TT + t;
        Y[s] = pack2(pred[o0] - targ[o0], pred[o1] - targ[o1]);
#pragma unroll
        for (int k = 0; k <= 2 * s; ++k)
            P[PIX(s, k)] = pack2(covb[(r0 * NN + k) * TT],
                                 covb[(r1 * NN + k) * TT]);
        P[PIX(s, 2 * s + 1)] = pack2(0.0f, covb[(r1 * NN + (2 * s + 1)) * TT]);
    }

    // ---- Packed right-looking Cholesky + fused forward solve.
    // Pivots >= 1 (Sigma = AA^T + I): rsqrt/log safe; det(Sigma) fits fp32.
    float pivprod = 1.0f;
    float quad    = 0.0f;
#pragma unroll
    for (int j = 0; j < NN; ++j) {
        const int js = j >> 1, jr = j & 1;

        float pa, pb;
        unpack2(P[PIX(js, j)], pa, pb);
        const float piv = jr ? pb : pa;        // diagonal (j,j)
        pivprod *= piv;
        const float invd  = rsqrtf(piv);
        const u64   invd2 = pack2(invd, invd);

        // scale column j (packed over row-pairs; dead lanes stay harmless)
#pragma unroll
        for (int s = js; s < 8; ++s) P[PIX(s, j)] = mul2(P[PIX(s, j)], invd2);

        // y[j] scale + quad; boundary row j+1 handled scalar inside the pair
        float ya, yb;
        unpack2(Y[js], ya, yb);
        float yj;
        if (jr == 0) {
            yj = ya * invd;
            quad = fmaf(yj, yj, quad);
            float la, lb;
            unpack2(P[PIX(js, j)], la, lb);    // lb = L[j+1][j] (scaled)
            yb = fmaf(-lb, yj, yb);
            Y[js] = pack2(yj, yb);
        } else {
            yj = yb * invd;
            quad = fmaf(yj, yj, quad);
            Y[js] = pack2(ya, yj);
        }
        const u64 myj2 = pack2(-yj, -yj);
#pragma unroll
        for (int s = js + 1; s < 8; ++s) Y[s] = fma2(P[PIX(s, j)], myj2, Y[s]);

        // trailing update: col k -= L[:,j] * L[k][j], packed over row-pairs
#pragma unroll
        for (int k = j + 1; k < NN; ++k) {
            const int ks = k >> 1, kr = k & 1;
            float ca, cb;
            unpack2(P[PIX(ks, j)], ca, cb);
            const float ck  = kr ? cb : ca;    // L[k][j]
            const u64   mck = pack2(-ck, -ck);
#pragma unroll
            for (int s = ks; s < 8; ++s)
                P[PIX(s, k)] = fma2(P[PIX(s, j)], mck, P[PIX(s, k)]);
        }
    }

    // pivprod = det(Sigma) >= 1, within fp32 range -> one __logf.
    float v = quad + __logf(pivprod);

    // ---- In-block reduction: warp shuffles + 4-warp smem combine
    const int lane = tid & 31;
    const int wid  = tid >> 5;
#pragma unroll
    for (int o = 16; o > 0; o >>= 1) v += __shfl_down_sync(0xffffffffu, v, o);

    __shared__ float warpsum[TPB / 32];
    __shared__ bool  isLast;
    if (lane == 0) warpsum[wid] = v;
    __syncthreads();

    if (tid == 0) {
        float s = warpsum[0] + warpsum[1] + warpsum[2] + warpsum[3];
        g_partials[bid] = s;
        __threadfence();
        unsigned int c = atomicAdd(&g_count, 1u);
        isLast = (c == (unsigned int)(GRID - 1));
    }
    __syncthreads();

    // Last arriving block performs the deterministic final sum (fixed order).
    if (isLast) {
        float s = 0.0f;
#pragma unroll 8
        for (int i = tid; i < GRID; i += TPB) s += g_partials[i];
#pragma unroll
        for (int o = 16; o > 0; o >>= 1) s += __shfl_down_sync(0xffffffffu, s, o);
        if (lane == 0) warpsum[wid] = s;
        __syncthreads();
        if (tid == 0) {
            out[0] = (warpsum[0] + warpsum[1] + warpsum[2] + warpsum[3])
                     * (1.0f / (float)(BB * TT));
            g_count = 0;   // reset for the next graph replay
        }
    }
}

extern "C" void kernel_launch(void* const* d_in, const int* in_sizes, int n_in,
                              void* d_out, int out_size)
{
    const float* pred = (const float*)d_in[0];   // prediction [B,N,T]
    const float* targ = (const float*)d_in[1];   // target     [B,N,T]
    const float* cov  = (const float*)d_in[2];   // cov        [B,N,N,T]
    float* out = (float*)d_out;

    gll_f32x2_kernel<<<GRID, TPB>>>(pred, targ, cov, out);
}